// round 12
// baseline (speedup 1.0000x reference)
#include <cuda_runtime.h>
#include <cuda_bf16.h>
#include <cstdint>

#define C_OUT  128
#define H_OUT  62
#define W_OUT  62
#define PIX_PER_IMG (H_OUT * W_OUT)            // 3844
#define NPIX  (64 * PIX_PER_IMG)               // 246016

// Scratch (static device arrays; no allocation)
__device__ float         g_u0[(size_t)NPIX * C_OUT];        // u0 pixel-major [p][128]
__device__ __nv_bfloat16 g_xh[(size_t)64 * 64 * 64 * 64];   // x transposed [b][h][w][ic], hi
__device__ __nv_bfloat16 g_xl[(size_t)64 * 64 * 64 * 64];   // lo
__device__ __nv_bfloat16 g_wh[9 * 128 * 72];                // W packed [s][o][ic(pad72)], hi
__device__ __nv_bfloat16 g_wl[9 * 128 * 72];                // lo

// ---------------------------------------------------------------------------
// helpers
// ---------------------------------------------------------------------------
__device__ __forceinline__ unsigned pack_bf16(float hi, float lo) {
    unsigned r;
    asm("cvt.rn.bf16x2.f32 %0, %1, %2;" : "=r"(r) : "f"(hi), "f"(lo));
    return r;
}
__device__ __forceinline__ unsigned bmax2_zero(unsigned v) {
    unsigned r;
    asm("max.bf16x2 %0, %1, %2;" : "=r"(r) : "r"(v), "r"(0u));
    return r;
}
__device__ __forceinline__ unsigned sm_u32(const void* p) {
    return (unsigned)__cvta_generic_to_shared(p);
}
__device__ __forceinline__ void ldmatrix_x4(unsigned& r0, unsigned& r1,
                                            unsigned& r2, unsigned& r3,
                                            unsigned addr) {
    asm volatile("ldmatrix.sync.aligned.m8n8.x4.shared.b16 {%0,%1,%2,%3}, [%4];"
                 : "=r"(r0), "=r"(r1), "=r"(r2), "=r"(r3) : "r"(addr));
}
__device__ __forceinline__ void mma_bf16(float& d0, float& d1, float& d2, float& d3,
                                         unsigned a0, unsigned a1, unsigned a2, unsigned a3,
                                         unsigned b0, unsigned b1) {
    asm volatile(
        "mma.sync.aligned.m16n8k16.row.col.f32.bf16.bf16.f32 "
        "{%0,%1,%2,%3}, {%4,%5,%6,%7}, {%8,%9}, {%0,%1,%2,%3};"
        : "+f"(d0), "+f"(d1), "+f"(d2), "+f"(d3)
        : "r"(a0), "r"(a1), "r"(a2), "r"(a3), "r"(b0), "r"(b1));
}

// ---------------------------------------------------------------------------
// prep_x: x[b][ic][h][w] fp32  ->  g_xh/g_xl [b][h][w][ic] bf16 (hi/lo split)
// ---------------------------------------------------------------------------
__global__ __launch_bounds__(256)
void prep_x(const float* __restrict__ x) {
    __shared__ float ts[64][65];
    const int b = blockIdx.y, h = blockIdx.x, tid = threadIdx.x;
    const float* src = x + (size_t)b * 262144 + h * 64;
    for (int i = tid; i < 4096; i += 256) {
        int ic = i >> 6, w_ = i & 63;
        ts[w_][ic] = src[(size_t)ic * 4096 + w_];
    }
    __syncthreads();
    const size_t ob = (size_t)b * 262144 + (size_t)h * 4096;
    for (int i = tid; i < 4096; i += 256) {
        int w_ = i >> 6, ic = i & 63;
        float v = ts[w_][ic];
        __nv_bfloat16 hi = __float2bfloat16(v);
        g_xh[ob + i] = hi;
        g_xl[ob + i] = __float2bfloat16(v - __bfloat162float(hi));
    }
}

// ---------------------------------------------------------------------------
// prep_w: wff[o][ic][ky][kx] fp32 -> g_wh/g_wl [s=ky*3+kx][o][ic pad 72] bf16
// ---------------------------------------------------------------------------
__global__ void prep_w(const float* __restrict__ wff) {
    int idx = blockIdx.x * 256 + threadIdx.x;
    if (idx >= 9 * 128 * 72) return;
    int s = idx / 9216, r = idx % 9216, o = r / 72, ic = r % 72;
    float v = (ic < 64) ? wff[o * 576 + ic * 9 + s] : 0.0f;
    __nv_bfloat16 hi = __float2bfloat16(v);
    g_wh[idx] = hi;
    g_wl[idx] = __float2bfloat16(v - __bfloat162float(hi));
}

// ---------------------------------------------------------------------------
// conv2: bf16x3 tensor-core conv. One block = one (b, y): 64 pixels x 128 oc.
// ---------------------------------------------------------------------------
__global__ __launch_bounds__(128, 2)
void conv2() {
    extern __shared__ __nv_bfloat16 sm[];
    __nv_bfloat16* xh = sm;            // [3][66][72] = 14256
    __nv_bfloat16* xl = xh + 14256;
    __nv_bfloat16* wh = xl + 14256;    // [128][72]  = 9216
    __nv_bfloat16* wl = wh + 9216;

    const int tid = threadIdx.x, w = tid >> 5, t = tid & 31;
    const int y = blockIdx.x, b = blockIdx.y;

    {
        const __nv_bfloat16* gh = g_xh + ((size_t)(b * 64 + y) << 12);
        const __nv_bfloat16* gl = g_xl + ((size_t)(b * 64 + y) << 12);
        for (int i = tid; i < 1536; i += 128) {
            int r = i >> 9, rem = i & 511;
            int w_ = rem >> 3, ic8 = (rem & 7) << 3;
            int go = (r << 12) + (w_ << 6) + ic8;
            int so = (r * 66 + w_) * 72 + ic8;
            *(uint4*)(xh + so) = *(const uint4*)(gh + go);
            *(uint4*)(xl + so) = *(const uint4*)(gl + go);
        }
        for (int i = tid; i < 432; i += 128) {
            int r = i / 144, c = (i % 144) / 72, k = i % 72;
            ((unsigned short*)xh)[(r * 66 + 64 + c) * 72 + k] = 0;
            ((unsigned short*)xl)[(r * 66 + 64 + c) * 72 + k] = 0;
        }
    }

    float d[4][4][4];
#pragma unroll
    for (int mt = 0; mt < 4; mt++)
#pragma unroll
        for (int nt = 0; nt < 4; nt++)
#pragma unroll
            for (int e = 0; e < 4; e++) d[mt][nt][e] = 0.0f;

    const int lm8 = t & 7, lt = t >> 3;
    const int a_row = (lt & 1) * 8 + lm8, a_k = (lt >> 1) * 8;
    const int b_row = (lt >> 1) * 8 + lm8, b_k = (lt & 1) * 8;
    const unsigned xh0 = sm_u32(xh), xl0 = sm_u32(xl);
    const unsigned wh0 = sm_u32(wh), wl0 = sm_u32(wl);

#pragma unroll 1
    for (int s = 0; s < 9; s++) {
        __syncthreads();
        for (int i = tid; i < 1152; i += 128) {
            int o = i / 9, ic8 = (i % 9) << 3;
            int so = o * 72 + ic8, go = (s * 128 + o) * 72 + ic8;
            *(uint4*)(wh + so) = *(const uint4*)(g_wh + go);
            *(uint4*)(wl + so) = *(const uint4*)(g_wl + go);
        }
        __syncthreads();

        const int ky = s / 3, kx = s - ky * 3;
        const unsigned ab_h = xh0 + (unsigned)((ky * 66 + kx) * 72 * 2);
        const unsigned ab_l = xl0 + (unsigned)((ky * 66 + kx) * 72 * 2);

#pragma unroll
        for (int kt = 0; kt < 4; kt++) {
            unsigned bh[4][2], bl[4][2];
            const unsigned wbo = (unsigned)(((w * 32 + b_row) * 72 + kt * 16 + b_k) * 2);
            ldmatrix_x4(bh[0][0], bh[0][1], bh[1][0], bh[1][1], wh0 + wbo);
            ldmatrix_x4(bh[2][0], bh[2][1], bh[3][0], bh[3][1], wh0 + wbo + 16 * 144);
            ldmatrix_x4(bl[0][0], bl[0][1], bl[1][0], bl[1][1], wl0 + wbo);
            ldmatrix_x4(bl[2][0], bl[2][1], bl[3][0], bl[3][1], wl0 + wbo + 16 * 144);
#pragma unroll
            for (int mt = 0; mt < 4; mt++) {
                const unsigned ao = (unsigned)(((mt * 16 + a_row) * 72 + kt * 16 + a_k) * 2);
                unsigned ah0, ah1, ah2, ah3, al0, al1, al2, al3;
                ldmatrix_x4(ah0, ah1, ah2, ah3, ab_h + ao);
                ldmatrix_x4(al0, al1, al2, al3, ab_l + ao);
#pragma unroll
                for (int nt = 0; nt < 4; nt++) {
                    mma_bf16(d[mt][nt][0], d[mt][nt][1], d[mt][nt][2], d[mt][nt][3],
                             ah0, ah1, ah2, ah3, bh[nt][0], bh[nt][1]);
                    mma_bf16(d[mt][nt][0], d[mt][nt][1], d[mt][nt][2], d[mt][nt][3],
                             ah0, ah1, ah2, ah3, bl[nt][0], bl[nt][1]);
                    mma_bf16(d[mt][nt][0], d[mt][nt][1], d[mt][nt][2], d[mt][nt][3],
                             al0, al1, al2, al3, bh[nt][0], bh[nt][1]);
                }
            }
        }
    }

    const int p0 = b * PIX_PER_IMG + y * W_OUT;
    const int q = t & 3, g = t >> 2;
#pragma unroll
    for (int mt = 0; mt < 4; mt++) {
#pragma unroll
        for (int nt = 0; nt < 4; nt++) {
            const int ch = w * 32 + nt * 8 + q * 2;
            const int m = mt * 16 + g;
            if (m < W_OUT)
                *(float2*)(g_u0 + (size_t)(p0 + m) * C_OUT + ch) =
                    make_float2(d[mt][nt][0], d[mt][nt][1]);
            if (m + 8 < W_OUT)
                *(float2*)(g_u0 + (size_t)(p0 + m + 8) * C_OUT + ch) =
                    make_float2(d[mt][nt][2], d[mt][nt][3]);
        }
    }
}

// ---------------------------------------------------------------------------
// iter_kernel v6: warp-pair scheme + own-half B (Wr) cached in registers.
// Per-iter LDSM: 4 partner-A + 16 partner-B = 20 (was 36). 2 blocks/SM.
// ---------------------------------------------------------------------------
__global__ __launch_bounds__(128, 2)
void iter_kernel(const float* __restrict__ wrec, const float* __restrict__ thrg,
                 float* __restrict__ out) {
    extern __shared__ __align__(16) unsigned short smem_i[];
    __shared__ float norm_s[2][2][2];   // [pair][hw][{sd,su}]

    const int tid = threadIdx.x;
    const int w = tid >> 5, t = tid & 31;
    const int pair = w >> 1, hw = w & 1;
    const int g = t >> 2, q = t & 3;
    const int p0 = (blockIdx.x * 2 + pair) * 16;

    unsigned short* wr = smem_i;                        // [128][136] bf16
    unsigned short* ax = smem_i + 17408 + pair * 4352;  // [2][16][136] bf16

    // ---- Wr -> smem bf16 (block-wide) ----
    for (int i = tid; i < 16384; i += 128)
        ((__nv_bfloat16*)wr)[(i >> 7) * 136 + (i & 127)] = __float2bfloat16(wrec[i]);

    // ---- init E = 5thr - u0, C = thr - u0, a0 = relu(u0) ----
    const int cbase = hw * 64 + 2 * q;
    float E[8][4], C[8][4];
    unsigned ownA[4][4];
    {
        const float* u0a = g_u0 + (size_t)(p0 + g) * C_OUT;
        const float* u0b = g_u0 + (size_t)(p0 + g + 8) * C_OUT;
#pragma unroll
        for (int nt = 0; nt < 8; nt++) {
            const int c = cbase + nt * 8;
            float2 th = *(const float2*)(thrg + c);
            float2 r0 = *(const float2*)(u0a + c);
            float2 r1 = *(const float2*)(u0b + c);
            E[nt][0] = 5.0f * th.x - r0.x; E[nt][1] = 5.0f * th.y - r0.y;
            E[nt][2] = 5.0f * th.x - r1.x; E[nt][3] = 5.0f * th.y - r1.y;
            C[nt][0] = th.x - r0.x; C[nt][1] = th.y - r0.y;
            C[nt][2] = th.x - r1.x; C[nt][3] = th.y - r1.y;
            unsigned plo = pack_bf16(fmaxf(r0.y, 0.0f), fmaxf(r0.x, 0.0f));
            unsigned phi = pack_bf16(fmaxf(r1.y, 0.0f), fmaxf(r1.x, 0.0f));
            *(unsigned*)(ax + g * 136 + c) = plo;
            *(unsigned*)(ax + (g + 8) * 136 + c) = phi;
            const int j = nt >> 1;
            if ((nt & 1) == 0) { ownA[j][0] = plo; ownA[j][1] = phi; }
            else               { ownA[j][2] = plo; ownA[j][3] = phi; }
        }
    }
    __syncthreads();   // Wr + all pairs' a0 visible

    // ---- lane addresses ----
    const int lm8 = t & 7, lt = t >> 3;
    // partner-A ldmatrix (rows = px): tiles r0-7/klo, r8-15/klo, r0-7/khi, r8-15/khi
    const unsigned aLane = sm_u32(ax) + (unsigned)((lm8 + 8 * (lt & 1)) * 272 + (t >> 4) * 16);
    // B ldmatrix (rows = oc): tiles (n0-7,klo),(n0-7,khi),(n8-15,klo),(n8-15,khi)
    const unsigned bLane = sm_u32(wr) +
        (unsigned)(((hw * 64 + (lt >> 1) * 8 + lm8) * 136 + (lt & 1) * 8) * 2);

    // ---- own-half B (static Wr fragments) cached in registers: 64 regs ----
    unsigned ownB[4][8][2];
#pragma unroll
    for (int j = 0; j < 4; j++) {
        const int kk = hw * 4 + j;
        ldmatrix_x4(ownB[j][0][0], ownB[j][0][1], ownB[j][1][0], ownB[j][1][1], bLane + kk * 32);
        ldmatrix_x4(ownB[j][2][0], ownB[j][2][1], ownB[j][3][0], ownB[j][3][1], bLane + kk * 32 + 4352);
        ldmatrix_x4(ownB[j][4][0], ownB[j][4][1], ownB[j][5][0], ownB[j][5][1], bLane + kk * 32 + 8704);
        ldmatrix_x4(ownB[j][6][0], ownB[j][6][1], ownB[j][7][0], ownB[j][7][1], bLane + kk * 32 + 13056);
    }

    const int kkp0 = (1 - hw) * 4;     // partner k-tile base
    const int bar_id = 1 + pair;

    float stash[4];
    int buf = 0;
    for (int it = 0; it < 200; it++) {
        // ---- own k-tiles: A from registers, B from cached registers ----
#pragma unroll
        for (int j = 0; j < 4; j++) {
#pragma unroll
            for (int nt = 0; nt < 8; nt++)
                mma_bf16(E[nt][0], E[nt][1], E[nt][2], E[nt][3],
                         ownA[j][0], ownA[j][1], ownA[j][2], ownA[j][3],
                         ownB[j][nt][0], ownB[j][nt][1]);
        }
        // ---- partner k-tiles: A + B via ldmatrix ----
#pragma unroll
        for (int j = 0; j < 4; j++) {
            const int kk = kkp0 + j;
            unsigned A0, A1, A2, A3;
            ldmatrix_x4(A0, A1, A2, A3, aLane + buf * 4352 + kk * 32);
            unsigned bb[8][2];
            ldmatrix_x4(bb[0][0], bb[0][1], bb[1][0], bb[1][1], bLane + kk * 32);
            ldmatrix_x4(bb[2][0], bb[2][1], bb[3][0], bb[3][1], bLane + kk * 32 + 4352);
            ldmatrix_x4(bb[4][0], bb[4][1], bb[5][0], bb[5][1], bLane + kk * 32 + 8704);
            ldmatrix_x4(bb[6][0], bb[6][1], bb[7][0], bb[7][1], bLane + kk * 32 + 13056);
#pragma unroll
            for (int nt = 0; nt < 8; nt++)
                mma_bf16(E[nt][0], E[nt][1], E[nt][2], E[nt][3],
                         A0, A1, A2, A3, bb[nt][0], bb[nt][1]);
        }

        // ---- epilogue: a_new = relu(-0.2E) -> regs (ownA) + smem (partner) ----
        const int nb = buf ^ 1;
#pragma unroll
        for (int nt = 0; nt < 8; nt++) {
            const int c = cbase + nt * 8;
            unsigned plo = bmax2_zero(pack_bf16(-0.2f * E[nt][1], -0.2f * E[nt][0]));
            unsigned phi = bmax2_zero(pack_bf16(-0.2f * E[nt][3], -0.2f * E[nt][2]));
            *(unsigned*)(ax + nb * 2176 + g * 136 + c) = plo;
            *(unsigned*)(ax + nb * 2176 + (g + 8) * 136 + c) = phi;
            const int j = nt >> 1;
            if ((nt & 1) == 0) { ownA[j][0] = plo; ownA[j][1] = phi; }
            else               { ownA[j][2] = plo; ownA[j][3] = phi; }
        }

        // ---- convergence bookkeeping (sample: nt=0) ----
        const bool check = (it & 1);
        if (check) {
            float sdu = 0.0f, sun = 0.0f;
#pragma unroll
            for (int e = 0; e < 4; e++) {
                float df = E[0][e] - stash[e];
                sdu = fmaf(df, df, sdu);
                sun = fmaf(E[0][e], E[0][e], sun);
            }
#pragma unroll
            for (int m = 16; m; m >>= 1) {
                sdu += __shfl_xor_sync(0xffffffffu, sdu, m);
                sun += __shfl_xor_sync(0xffffffffu, sun, m);
            }
            if (t == 0) { norm_s[pair][hw][0] = sdu; norm_s[pair][hw][1] = sun; }
        } else {
#pragma unroll
            for (int e = 0; e < 4; e++) stash[e] = E[0][e];
        }

        // ---- pair barrier (2 warps) ----
        asm volatile("bar.sync %0, 64;" :: "r"(bar_id) : "memory");

        if (check) {
            float SD = norm_s[pair][0][0] + norm_s[pair][1][0];
            float SU = norm_s[pair][0][1] + norm_s[pair][1][1];
            if (SD <= 1.0e-8f * SU) break;
        }

        // ---- seed: E = 0.8E + (thr - u0) ----
#pragma unroll
        for (int nt = 0; nt < 8; nt++)
#pragma unroll
            for (int e = 0; e < 4; e++)
                E[nt][e] = fmaf(0.8f, E[nt][e], C[nt][e]);
        buf = nb;
    }

    // ---- final store: out = relu(-0.2E), restage [oc][17] then NCHW ----
    float* stage = reinterpret_cast<float*>(ax);   // 128*17*4 = 8704 B, exact alias
#pragma unroll
    for (int nt = 0; nt < 8; nt++) {
        const int c = cbase + nt * 8;
        stage[c * 17 + g]           = fmaxf(-0.2f * E[nt][0], 0.0f);
        stage[(c + 1) * 17 + g]     = fmaxf(-0.2f * E[nt][1], 0.0f);
        stage[c * 17 + g + 8]       = fmaxf(-0.2f * E[nt][2], 0.0f);
        stage[(c + 1) * 17 + g + 8] = fmaxf(-0.2f * E[nt][3], 0.0f);
    }
    __syncwarp();

#pragma unroll
    for (int r = 0; r < 2; r++) {
        const int oc = hw * 64 + r * 32 + t;
        int bb2 = p0 / PIX_PER_IMG;
        int rem = p0 - bb2 * PIX_PER_IMG;
#pragma unroll
        for (int e = 0; e < 16; e++) {
            out[((size_t)bb2 * C_OUT + oc) * PIX_PER_IMG + rem] = stage[oc * 17 + e];
            if (++rem == PIX_PER_IMG) { rem = 0; bb2++; }
        }
    }
}

// ---------------------------------------------------------------------------
extern "C" void kernel_launch(void* const* d_in, const int* in_sizes, int n_in,
                              void* d_out, int out_size) {
    const float* x    = (const float*)d_in[0];   // (64,64,64,64)
    const float* wff  = (const float*)d_in[1];   // (128,64,3,3)
    const float* wrec = (const float*)d_in[2];   // (128,128,1,1)
    const float* thr  = (const float*)d_in[3];   // (128,)
    float* out = (float*)d_out;                  // (64,128,62,62)

    cudaFuncSetAttribute(conv2, cudaFuncAttributeMaxDynamicSharedMemorySize, 93888);
    cudaFuncSetAttribute(iter_kernel, cudaFuncAttributeMaxDynamicSharedMemorySize, 52224);

    prep_x<<<dim3(64, 64), 256>>>(x);
    prep_w<<<(9 * 128 * 72 + 255) / 256, 256>>>(wff);
    conv2<<<dim3(H_OUT, 64), 128, 93888>>>();
    iter_kernel<<<NPIX / 32, 128, 52224>>>(wrec, thr, out);
}

// round 14
// speedup vs baseline: 1.1847x; 1.1847x over previous
#include <cuda_runtime.h>
#include <cuda_bf16.h>
#include <cstdint>

#define C_OUT  128
#define H_OUT  62
#define W_OUT  62
#define PIX_PER_IMG (H_OUT * W_OUT)            // 3844
#define NPIX  (64 * PIX_PER_IMG)               // 246016

// Scratch (static device arrays; no allocation)
__device__ float         g_u0[(size_t)NPIX * C_OUT];        // u0 pixel-major [p][128]
__device__ __nv_bfloat16 g_xh[(size_t)64 * 64 * 64 * 64];   // x transposed [b][h][w][ic], hi
__device__ __nv_bfloat16 g_xl[(size_t)64 * 64 * 64 * 64];   // lo
__device__ __nv_bfloat16 g_wh[9 * 128 * 72];                // W packed [s][o][ic(pad72)], hi
__device__ __nv_bfloat16 g_wl[9 * 128 * 72];                // lo

// ---------------------------------------------------------------------------
// helpers
// ---------------------------------------------------------------------------
__device__ __forceinline__ unsigned pack_bf16(float hi, float lo) {
    unsigned r;
    asm("cvt.rn.bf16x2.f32 %0, %1, %2;" : "=r"(r) : "f"(hi), "f"(lo));
    return r;
}
__device__ __forceinline__ unsigned bmax2_zero(unsigned v) {
    unsigned r;
    asm("max.bf16x2 %0, %1, %2;" : "=r"(r) : "r"(v), "r"(0u));
    return r;
}
__device__ __forceinline__ unsigned sm_u32(const void* p) {
    return (unsigned)__cvta_generic_to_shared(p);
}
__device__ __forceinline__ void ldmatrix_x4(unsigned& r0, unsigned& r1,
                                            unsigned& r2, unsigned& r3,
                                            unsigned addr) {
    asm volatile("ldmatrix.sync.aligned.m8n8.x4.shared.b16 {%0,%1,%2,%3}, [%4];"
                 : "=r"(r0), "=r"(r1), "=r"(r2), "=r"(r3) : "r"(addr));
}
__device__ __forceinline__ void mma_bf16(float& d0, float& d1, float& d2, float& d3,
                                         unsigned a0, unsigned a1, unsigned a2, unsigned a3,
                                         unsigned b0, unsigned b1) {
    asm volatile(
        "mma.sync.aligned.m16n8k16.row.col.f32.bf16.bf16.f32 "
        "{%0,%1,%2,%3}, {%4,%5,%6,%7}, {%8,%9}, {%0,%1,%2,%3};"
        : "+f"(d0), "+f"(d1), "+f"(d2), "+f"(d3)
        : "r"(a0), "r"(a1), "r"(a2), "r"(a3), "r"(b0), "r"(b1));
}

// ---------------------------------------------------------------------------
// prep_x: x[b][ic][h][w] fp32  ->  g_xh/g_xl [b][h][w][ic] bf16 (hi/lo split)
// ---------------------------------------------------------------------------
__global__ __launch_bounds__(256)
void prep_x(const float* __restrict__ x) {
    __shared__ float ts[64][65];
    const int b = blockIdx.y, h = blockIdx.x, tid = threadIdx.x;
    const float* src = x + (size_t)b * 262144 + h * 64;
    for (int i = tid; i < 4096; i += 256) {
        int ic = i >> 6, w_ = i & 63;
        ts[w_][ic] = src[(size_t)ic * 4096 + w_];
    }
    __syncthreads();
    const size_t ob = (size_t)b * 262144 + (size_t)h * 4096;
    for (int i = tid; i < 4096; i += 256) {
        int w_ = i >> 6, ic = i & 63;
        float v = ts[w_][ic];
        __nv_bfloat16 hi = __float2bfloat16(v);
        g_xh[ob + i] = hi;
        g_xl[ob + i] = __float2bfloat16(v - __bfloat162float(hi));
    }
}

// ---------------------------------------------------------------------------
// prep_w: wff[o][ic][ky][kx] fp32 -> g_wh/g_wl [s=ky*3+kx][o][ic pad 72] bf16
// ---------------------------------------------------------------------------
__global__ void prep_w(const float* __restrict__ wff) {
    int idx = blockIdx.x * 256 + threadIdx.x;
    if (idx >= 9 * 128 * 72) return;
    int s = idx / 9216, r = idx % 9216, o = r / 72, ic = r % 72;
    float v = (ic < 64) ? wff[o * 576 + ic * 9 + s] : 0.0f;
    __nv_bfloat16 hi = __float2bfloat16(v);
    g_wh[idx] = hi;
    g_wl[idx] = __float2bfloat16(v - __bfloat162float(hi));
}

// ---------------------------------------------------------------------------
// conv2: bf16x3 tensor-core conv. One block = one (b, y): 64 pixels x 128 oc.
// ---------------------------------------------------------------------------
__global__ __launch_bounds__(128, 2)
void conv2() {
    extern __shared__ __nv_bfloat16 sm[];
    __nv_bfloat16* xh = sm;            // [3][66][72] = 14256
    __nv_bfloat16* xl = xh + 14256;
    __nv_bfloat16* wh = xl + 14256;    // [128][72]  = 9216
    __nv_bfloat16* wl = wh + 9216;

    const int tid = threadIdx.x, w = tid >> 5, t = tid & 31;
    const int y = blockIdx.x, b = blockIdx.y;

    {
        const __nv_bfloat16* gh = g_xh + ((size_t)(b * 64 + y) << 12);
        const __nv_bfloat16* gl = g_xl + ((size_t)(b * 64 + y) << 12);
        for (int i = tid; i < 1536; i += 128) {
            int r = i >> 9, rem = i & 511;
            int w_ = rem >> 3, ic8 = (rem & 7) << 3;
            int go = (r << 12) + (w_ << 6) + ic8;
            int so = (r * 66 + w_) * 72 + ic8;
            *(uint4*)(xh + so) = *(const uint4*)(gh + go);
            *(uint4*)(xl + so) = *(const uint4*)(gl + go);
        }
        for (int i = tid; i < 432; i += 128) {
            int r = i / 144, c = (i % 144) / 72, k = i % 72;
            ((unsigned short*)xh)[(r * 66 + 64 + c) * 72 + k] = 0;
            ((unsigned short*)xl)[(r * 66 + 64 + c) * 72 + k] = 0;
        }
    }

    float d[4][4][4];
#pragma unroll
    for (int mt = 0; mt < 4; mt++)
#pragma unroll
        for (int nt = 0; nt < 4; nt++)
#pragma unroll
            for (int e = 0; e < 4; e++) d[mt][nt][e] = 0.0f;

    const int lm8 = t & 7, lt = t >> 3;
    const int a_row = (lt & 1) * 8 + lm8, a_k = (lt >> 1) * 8;
    const int b_row = (lt >> 1) * 8 + lm8, b_k = (lt & 1) * 8;
    const unsigned xh0 = sm_u32(xh), xl0 = sm_u32(xl);
    const unsigned wh0 = sm_u32(wh), wl0 = sm_u32(wl);

#pragma unroll 1
    for (int s = 0; s < 9; s++) {
        __syncthreads();
        for (int i = tid; i < 1152; i += 128) {
            int o = i / 9, ic8 = (i % 9) << 3;
            int so = o * 72 + ic8, go = (s * 128 + o) * 72 + ic8;
            *(uint4*)(wh + so) = *(const uint4*)(g_wh + go);
            *(uint4*)(wl + so) = *(const uint4*)(g_wl + go);
        }
        __syncthreads();

        const int ky = s / 3, kx = s - ky * 3;
        const unsigned ab_h = xh0 + (unsigned)((ky * 66 + kx) * 72 * 2);
        const unsigned ab_l = xl0 + (unsigned)((ky * 66 + kx) * 72 * 2);

#pragma unroll
        for (int kt = 0; kt < 4; kt++) {
            unsigned bh[4][2], bl[4][2];
            const unsigned wbo = (unsigned)(((w * 32 + b_row) * 72 + kt * 16 + b_k) * 2);
            ldmatrix_x4(bh[0][0], bh[0][1], bh[1][0], bh[1][1], wh0 + wbo);
            ldmatrix_x4(bh[2][0], bh[2][1], bh[3][0], bh[3][1], wh0 + wbo + 16 * 144);
            ldmatrix_x4(bl[0][0], bl[0][1], bl[1][0], bl[1][1], wl0 + wbo);
            ldmatrix_x4(bl[2][0], bl[2][1], bl[3][0], bl[3][1], wl0 + wbo + 16 * 144);
#pragma unroll
            for (int mt = 0; mt < 4; mt++) {
                const unsigned ao = (unsigned)(((mt * 16 + a_row) * 72 + kt * 16 + a_k) * 2);
                unsigned ah0, ah1, ah2, ah3, al0, al1, al2, al3;
                ldmatrix_x4(ah0, ah1, ah2, ah3, ab_h + ao);
                ldmatrix_x4(al0, al1, al2, al3, ab_l + ao);
#pragma unroll
                for (int nt = 0; nt < 4; nt++) {
                    mma_bf16(d[mt][nt][0], d[mt][nt][1], d[mt][nt][2], d[mt][nt][3],
                             ah0, ah1, ah2, ah3, bh[nt][0], bh[nt][1]);
                    mma_bf16(d[mt][nt][0], d[mt][nt][1], d[mt][nt][2], d[mt][nt][3],
                             ah0, ah1, ah2, ah3, bl[nt][0], bl[nt][1]);
                    mma_bf16(d[mt][nt][0], d[mt][nt][1], d[mt][nt][2], d[mt][nt][3],
                             al0, al1, al2, al3, bh[nt][0], bh[nt][1]);
                }
            }
        }
    }

    const int p0 = b * PIX_PER_IMG + y * W_OUT;
    const int q = t & 3, g = t >> 2;
#pragma unroll
    for (int mt = 0; mt < 4; mt++) {
#pragma unroll
        for (int nt = 0; nt < 4; nt++) {
            const int ch = w * 32 + nt * 8 + q * 2;
            const int m = mt * 16 + g;
            if (m < W_OUT)
                *(float2*)(g_u0 + (size_t)(p0 + m) * C_OUT + ch) =
                    make_float2(d[mt][nt][0], d[mt][nt][1]);
            if (m + 8 < W_OUT)
                *(float2*)(g_u0 + (size_t)(p0 + m + 8) * C_OUT + ch) =
                    make_float2(d[mt][nt][2], d[mt][nt][3]);
        }
    }
}

// ---------------------------------------------------------------------------
// iter_kernel v7: warp-pair scheme + HALF of own-B cached in regs (2 of 4
// k-tiles, 32 regs). Per-iter LDSM: 28 (was 36 in v5, 20 in v6). Target 3
// blocks/SM (12 warps): midpoint of v5 (LDSM-bound) and v6 (latency-bound).
// ---------------------------------------------------------------------------
__global__ __launch_bounds__(128, 3)
void iter_kernel(const float* __restrict__ wrec, const float* __restrict__ thrg,
                 float* __restrict__ out) {
    extern __shared__ __align__(16) unsigned short smem_i[];
    __shared__ float norm_s[2][2][2];   // [pair][hw][{sd,su}]

    const int tid = threadIdx.x;
    const int w = tid >> 5, t = tid & 31;
    const int pair = w >> 1, hw = w & 1;
    const int g = t >> 2, q = t & 3;
    const int p0 = (blockIdx.x * 2 + pair) * 16;

    unsigned short* wr = smem_i;                        // [128][136] bf16
    unsigned short* ax = smem_i + 17408 + pair * 4352;  // [2][16][136] bf16

    // ---- Wr -> smem bf16 (block-wide) ----
    for (int i = tid; i < 16384; i += 128)
        ((__nv_bfloat16*)wr)[(i >> 7) * 136 + (i & 127)] = __float2bfloat16(wrec[i]);

    // ---- init E = 5thr - u0, C = thr - u0, a0 = relu(u0) ----
    const int cbase = hw * 64 + 2 * q;
    float E[8][4], C[8][4];
    unsigned ownA[4][4];
    {
        const float* u0a = g_u0 + (size_t)(p0 + g) * C_OUT;
        const float* u0b = g_u0 + (size_t)(p0 + g + 8) * C_OUT;
#pragma unroll
        for (int nt = 0; nt < 8; nt++) {
            const int c = cbase + nt * 8;
            float2 th = *(const float2*)(thrg + c);
            float2 r0 = *(const float2*)(u0a + c);
            float2 r1 = *(const float2*)(u0b + c);
            E[nt][0] = 5.0f * th.x - r0.x; E[nt][1] = 5.0f * th.y - r0.y;
            E[nt][2] = 5.0f * th.x - r1.x; E[nt][3] = 5.0f * th.y - r1.y;
            C[nt][0] = th.x - r0.x; C[nt][1] = th.y - r0.y;
            C[nt][2] = th.x - r1.x; C[nt][3] = th.y - r1.y;
            unsigned plo = pack_bf16(fmaxf(r0.y, 0.0f), fmaxf(r0.x, 0.0f));
            unsigned phi = pack_bf16(fmaxf(r1.y, 0.0f), fmaxf(r1.x, 0.0f));
            *(unsigned*)(ax + g * 136 + c) = plo;
            *(unsigned*)(ax + (g + 8) * 136 + c) = phi;
            const int j = nt >> 1;
            if ((nt & 1) == 0) { ownA[j][0] = plo; ownA[j][1] = phi; }
            else               { ownA[j][2] = plo; ownA[j][3] = phi; }
        }
    }
    __syncthreads();   // Wr + all pairs' a0 visible

    // ---- lane addresses ----
    const int lm8 = t & 7, lt = t >> 3;
    // partner-A ldmatrix (rows = px): tiles r0-7/klo, r8-15/klo, r0-7/khi, r8-15/khi
    const unsigned aLane = sm_u32(ax) + (unsigned)((lm8 + 8 * (lt & 1)) * 272 + (t >> 4) * 16);
    // B ldmatrix (rows = oc): tiles (n0-7,klo),(n0-7,khi),(n8-15,klo),(n8-15,khi)
    const unsigned bLane = sm_u32(wr) +
        (unsigned)(((hw * 64 + (lt >> 1) * 8 + lm8) * 136 + (lt & 1) * 8) * 2);

    // ---- partial own-B cache: k-tiles j=0,1 (32 regs) ----
    unsigned ownB[2][8][2];
#pragma unroll
    for (int j = 0; j < 2; j++) {
        const int kk = hw * 4 + j;
        ldmatrix_x4(ownB[j][0][0], ownB[j][0][1], ownB[j][1][0], ownB[j][1][1], bLane + kk * 32);
        ldmatrix_x4(ownB[j][2][0], ownB[j][2][1], ownB[j][3][0], ownB[j][3][1], bLane + kk * 32 + 4352);
        ldmatrix_x4(ownB[j][4][0], ownB[j][4][1], ownB[j][5][0], ownB[j][5][1], bLane + kk * 32 + 8704);
        ldmatrix_x4(ownB[j][6][0], ownB[j][6][1], ownB[j][7][0], ownB[j][7][1], bLane + kk * 32 + 13056);
    }

    const int kkp0 = (1 - hw) * 4;     // partner k-tile base
    const int bar_id = 1 + pair;

    float stash[4];
    int buf = 0;
    for (int it = 0; it < 200; it++) {
        // ---- own k-tiles j=0,1: A + B both from registers ----
#pragma unroll
        for (int j = 0; j < 2; j++) {
#pragma unroll
            for (int nt = 0; nt < 8; nt++)
                mma_bf16(E[nt][0], E[nt][1], E[nt][2], E[nt][3],
                         ownA[j][0], ownA[j][1], ownA[j][2], ownA[j][3],
                         ownB[j][nt][0], ownB[j][nt][1]);
        }
        // ---- own k-tiles j=2,3: A from registers, B via ldmatrix ----
#pragma unroll
        for (int j = 2; j < 4; j++) {
            const int kk = hw * 4 + j;
            unsigned bb[8][2];
            ldmatrix_x4(bb[0][0], bb[0][1], bb[1][0], bb[1][1], bLane + kk * 32);
            ldmatrix_x4(bb[2][0], bb[2][1], bb[3][0], bb[3][1], bLane + kk * 32 + 4352);
            ldmatrix_x4(bb[4][0], bb[4][1], bb[5][0], bb[5][1], bLane + kk * 32 + 8704);
            ldmatrix_x4(bb[6][0], bb[6][1], bb[7][0], bb[7][1], bLane + kk * 32 + 13056);
#pragma unroll
            for (int nt = 0; nt < 8; nt++)
                mma_bf16(E[nt][0], E[nt][1], E[nt][2], E[nt][3],
                         ownA[j][0], ownA[j][1], ownA[j][2], ownA[j][3],
                         bb[nt][0], bb[nt][1]);
        }
        // ---- partner k-tiles: A + B via ldmatrix ----
#pragma unroll
        for (int j = 0; j < 4; j++) {
            const int kk = kkp0 + j;
            unsigned A0, A1, A2, A3;
            ldmatrix_x4(A0, A1, A2, A3, aLane + buf * 4352 + kk * 32);
            unsigned bb[8][2];
            ldmatrix_x4(bb[0][0], bb[0][1], bb[1][0], bb[1][1], bLane + kk * 32);
            ldmatrix_x4(bb[2][0], bb[2][1], bb[3][0], bb[3][1], bLane + kk * 32 + 4352);
            ldmatrix_x4(bb[4][0], bb[4][1], bb[5][0], bb[5][1], bLane + kk * 32 + 8704);
            ldmatrix_x4(bb[6][0], bb[6][1], bb[7][0], bb[7][1], bLane + kk * 32 + 13056);
#pragma unroll
            for (int nt = 0; nt < 8; nt++)
                mma_bf16(E[nt][0], E[nt][1], E[nt][2], E[nt][3],
                         A0, A1, A2, A3, bb[nt][0], bb[nt][1]);
        }

        // ---- epilogue: a_new = relu(-0.2E) -> regs (ownA) + smem (partner) ----
        const int nb = buf ^ 1;
#pragma unroll
        for (int nt = 0; nt < 8; nt++) {
            const int c = cbase + nt * 8;
            unsigned plo = bmax2_zero(pack_bf16(-0.2f * E[nt][1], -0.2f * E[nt][0]));
            unsigned phi = bmax2_zero(pack_bf16(-0.2f * E[nt][3], -0.2f * E[nt][2]));
            *(unsigned*)(ax + nb * 2176 + g * 136 + c) = plo;
            *(unsigned*)(ax + nb * 2176 + (g + 8) * 136 + c) = phi;
            const int j = nt >> 1;
            if ((nt & 1) == 0) { ownA[j][0] = plo; ownA[j][1] = phi; }
            else               { ownA[j][2] = plo; ownA[j][3] = phi; }
        }

        // ---- convergence bookkeeping (sample: nt=0) ----
        const bool check = (it & 1);
        if (check) {
            float sdu = 0.0f, sun = 0.0f;
#pragma unroll
            for (int e = 0; e < 4; e++) {
                float df = E[0][e] - stash[e];
                sdu = fmaf(df, df, sdu);
                sun = fmaf(E[0][e], E[0][e], sun);
            }
#pragma unroll
            for (int m = 16; m; m >>= 1) {
                sdu += __shfl_xor_sync(0xffffffffu, sdu, m);
                sun += __shfl_xor_sync(0xffffffffu, sun, m);
            }
            if (t == 0) { norm_s[pair][hw][0] = sdu; norm_s[pair][hw][1] = sun; }
        } else {
#pragma unroll
            for (int e = 0; e < 4; e++) stash[e] = E[0][e];
        }

        // ---- pair barrier (2 warps) ----
        asm volatile("bar.sync %0, 64;" :: "r"(bar_id) : "memory");

        if (check) {
            float SD = norm_s[pair][0][0] + norm_s[pair][1][0];
            float SU = norm_s[pair][0][1] + norm_s[pair][1][1];
            if (SD <= 1.0e-8f * SU) break;
        }

        // ---- seed: E = 0.8E + (thr - u0) ----
#pragma unroll
        for (int nt = 0; nt < 8; nt++)
#pragma unroll
            for (int e = 0; e < 4; e++)
                E[nt][e] = fmaf(0.8f, E[nt][e], C[nt][e]);
        buf = nb;
    }

    // ---- final store: out = relu(-0.2E), restage [oc][17] then NCHW ----
    float* stage = reinterpret_cast<float*>(ax);   // 128*17*4 = 8704 B, exact alias
#pragma unroll
    for (int nt = 0; nt < 8; nt++) {
        const int c = cbase + nt * 8;
        stage[c * 17 + g]           = fmaxf(-0.2f * E[nt][0], 0.0f);
        stage[(c + 1) * 17 + g]     = fmaxf(-0.2f * E[nt][1], 0.0f);
        stage[c * 17 + g + 8]       = fmaxf(-0.2f * E[nt][2], 0.0f);
        stage[(c + 1) * 17 + g + 8] = fmaxf(-0.2f * E[nt][3], 0.0f);
    }
    __syncwarp();

#pragma unroll
    for (int r = 0; r < 2; r++) {
        const int oc = hw * 64 + r * 32 + t;
        int bb2 = p0 / PIX_PER_IMG;
        int rem = p0 - bb2 * PIX_PER_IMG;
#pragma unroll
        for (int e = 0; e < 16; e++) {
            out[((size_t)bb2 * C_OUT + oc) * PIX_PER_IMG + rem] = stage[oc * 17 + e];
            if (++rem == PIX_PER_IMG) { rem = 0; bb2++; }
        }
    }
}

// ---------------------------------------------------------------------------
extern "C" void kernel_launch(void* const* d_in, const int* in_sizes, int n_in,
                              void* d_out, int out_size) {
    const float* x    = (const float*)d_in[0];   // (64,64,64,64)
    const float* wff  = (const float*)d_in[1];   // (128,64,3,3)
    const float* wrec = (const float*)d_in[2];   // (128,128,1,1)
    const float* thr  = (const float*)d_in[3];   // (128,)
    float* out = (float*)d_out;                  // (64,128,62,62)

    cudaFuncSetAttribute(conv2, cudaFuncAttributeMaxDynamicSharedMemorySize, 93888);
    cudaFuncSetAttribute(iter_kernel, cudaFuncAttributeMaxDynamicSharedMemorySize, 52224);

    prep_x<<<dim3(64, 64), 256>>>(x);
    prep_w<<<(9 * 128 * 72 + 255) / 256, 256>>>(wff);
    conv2<<<dim3(H_OUT, 64), 128, 93888>>>();
    iter_kernel<<<NPIX / 32, 128, 52224>>>(wrec, thr, out);
}